// round 7
// baseline (speedup 1.0000x reference)
#include <cuda_runtime.h>
#include <cstdint>
#include <math.h>

// Problem constants
#define BB 4
#define SS 2048
#define DD 1024
#define HH 8
#define DHH 128
#define DFF 4096
#define ROWS (BB*SS)   // 8192

// -------- scratch buffers (device globals; no allocation allowed) --------
// IMPORTANT: these are ONLY ever referenced from device code (template-selected
// inside kernels). Never passed by name from host code — the host shadow
// symbol is a host address (GB300 ATS makes it silently dereferenceable!).
__device__ float g_qkv [ROWS * 3 * DD];   // 96 MB
__device__ float g_attn[ROWS * DD];       // 32 MB
__device__ float g_x   [ROWS * DD];       // 32 MB
__device__ float g_ff1 [ROWS * DFF];      // 128 MB
__device__ float g_tmp [ROWS * DD];       // 32 MB

// ============================================================================
// SGEMM: C[M,N] = A[M,K] @ B[K,N]  (+bias, +relu per EPI flag)
// A selected by ASEL: 0=arg, 1=g_attn, 2=g_x, 3=g_ff1
// C selected by CSEL: 0=g_qkv, 1=g_tmp, 2=g_ff1
// 128x128 block tile, BK=8, 256 threads, 8x8 micro-tile split as 2x(4-wide)
// halves at column offsets {tx*4, 64+tx*4} for conflict-free broadcast LDS.
// ============================================================================
template<int EPI, int ASEL, int CSEL>
__global__ __launch_bounds__(256) void sgemm_kernel(
    const float* __restrict__ Aarg, const float* __restrict__ B,
    const float* __restrict__ bias, int M, int N, int K)
{
    const float* __restrict__ A =
        (ASEL == 0) ? Aarg : (ASEL == 1) ? g_attn : (ASEL == 2) ? g_x : g_ff1;
    float* __restrict__ C =
        (CSEL == 0) ? g_qkv : (CSEL == 1) ? g_tmp : g_ff1;

    __shared__ float As[8][128];
    __shared__ float Bs[8][128];

    const int tid = threadIdx.x;
    const int bx = blockIdx.x, by = blockIdx.y;
    const int tx = tid & 15;      // N direction (16)
    const int ty = tid >> 4;      // M direction (16)

    const int arow = tid >> 1;           // 0..127
    const int acol = (tid & 1) * 4;      // 0 or 4
    const int brow = tid >> 5;           // 0..7
    const int bcol = (tid & 31) * 4;     // 0..124

    const float* Ab = A + (size_t)by * 128 * K;
    const float* Bb = B + (size_t)bx * 128;

    float acc[8][8];
#pragma unroll
    for (int i = 0; i < 8; i++)
#pragma unroll
        for (int j = 0; j < 8; j++) acc[i][j] = 0.f;

    for (int k0 = 0; k0 < K; k0 += 8) {
        float4 av = *(const float4*)(Ab + (size_t)arow * K + k0 + acol);
        As[acol + 0][arow] = av.x;
        As[acol + 1][arow] = av.y;
        As[acol + 2][arow] = av.z;
        As[acol + 3][arow] = av.w;
        *(float4*)&Bs[brow][bcol] =
            *(const float4*)(Bb + (size_t)(k0 + brow) * N + bcol);
        __syncthreads();

#pragma unroll
        for (int k = 0; k < 8; k++) {
            float4 a0 = ((const float4*)As[k])[ty];
            float4 a1 = ((const float4*)As[k])[16 + ty];
            float4 b0 = ((const float4*)Bs[k])[tx];
            float4 b1 = ((const float4*)Bs[k])[16 + tx];
            float ar[8] = {a0.x,a0.y,a0.z,a0.w, a1.x,a1.y,a1.z,a1.w};
            float br[8] = {b0.x,b0.y,b0.z,b0.w, b1.x,b1.y,b1.z,b1.w};
#pragma unroll
            for (int i = 0; i < 8; i++)
#pragma unroll
                for (int j = 0; j < 8; j++)
                    acc[i][j] = fmaf(ar[i], br[j], acc[i][j]);
        }
        __syncthreads();
    }

    // epilogue: rows {ty*4+i, 64+ty*4+i}, cols {tx*4+j, 64+tx*4+j}
#pragma unroll
    for (int ih = 0; ih < 2; ih++) {
#pragma unroll
        for (int i = 0; i < 4; i++) {
            int rrow = by * 128 + ih * 64 + ty * 4 + i;
            float* crow = C + (size_t)rrow * N + bx * 128;
#pragma unroll
            for (int jh = 0; jh < 2; jh++) {
                int c0 = jh * 64 + tx * 4;
                float4 v;
                v.x = acc[ih*4 + i][jh*4 + 0];
                v.y = acc[ih*4 + i][jh*4 + 1];
                v.z = acc[ih*4 + i][jh*4 + 2];
                v.w = acc[ih*4 + i][jh*4 + 3];
                if (EPI >= 1) {
                    float4 bv = *(const float4*)(bias + bx * 128 + c0);
                    v.x += bv.x; v.y += bv.y; v.z += bv.z; v.w += bv.w;
                    if (EPI == 2) {
                        v.x = fmaxf(v.x, 0.f); v.y = fmaxf(v.y, 0.f);
                        v.z = fmaxf(v.z, 0.f); v.w = fmaxf(v.w, 0.f);
                    }
                }
                *(float4*)(crow + c0) = v;
            }
        }
    }
}

// ============================================================================
// Causal flash attention. Grid (S/64, H, B), 256 threads.
// Thread (row=tid/4, quad=tid&3) owns cols {quad*4 + 16*cc} (8 float4 chunks).
// Q,O in registers; K,V 32-key tiles in smem; online softmax.
// Reads g_qkv, writes g_attn (device symbols, referenced in device code).
// ============================================================================
__global__ __launch_bounds__(256) void attn_kernel()
{
    __shared__ float4 Kt[32][32];   // [key][128 floats as 32 float4]
    __shared__ float4 Vt[32][32];

    const float* __restrict__ qkv = g_qkv;
    float* __restrict__ out = g_attn;

    const int b = blockIdx.z, h = blockIdx.y, qt = blockIdx.x;
    const int tid = threadIdx.x;
    const int row = tid >> 2, quad = tid & 3;
    const int qrow = qt * 64 + row;
    const float scale = 0.08838834764831845f;   // 1/sqrt(128)

    const float* qbase = qkv + (size_t)(b * SS + qrow) * (3 * DD) + h * DHH;
    float4 q[8];
#pragma unroll
    for (int cc = 0; cc < 8; cc++) {
        float4 t = *(const float4*)(qbase + cc * 16 + quad * 4);
        t.x *= scale; t.y *= scale; t.z *= scale; t.w *= scale;
        q[cc] = t;
    }

    float4 o[8];
#pragma unroll
    for (int cc = 0; cc < 8; cc++) o[cc] = make_float4(0.f, 0.f, 0.f, 0.f);
    float m = -1e30f, l = 0.f;

    const int ntiles = 2 * qt + 2;   // keys [0, 64*qt+64) cover all qrow in tile
    for (int kt = 0; kt < ntiles; kt++) {
        const int kb = kt * 32;
        __syncthreads();
#pragma unroll
        for (int i = 0; i < 4; i++) {
            int f = tid + i * 256;
            int r = f >> 5, c = f & 31;
            size_t grow = (size_t)(b * SS + kb + r) * (3 * DD) + h * DHH;
            Kt[r][c] = *(const float4*)(qkv + grow + DD + c * 4);
            Vt[r][c] = *(const float4*)(qkv + grow + 2 * DD + c * 4);
        }
        __syncthreads();

        float s[32];
#pragma unroll
        for (int j = 0; j < 32; j++) {
            float a = 0.f;
#pragma unroll
            for (int cc = 0; cc < 8; cc++) {
                float4 kv = Kt[j][cc * 4 + quad];
                a = fmaf(q[cc].x, kv.x, a);
                a = fmaf(q[cc].y, kv.y, a);
                a = fmaf(q[cc].z, kv.z, a);
                a = fmaf(q[cc].w, kv.w, a);
            }
            a += __shfl_xor_sync(0xffffffffu, a, 1);
            a += __shfl_xor_sync(0xffffffffu, a, 2);
            s[j] = a;
        }
        if (kb + 31 > qrow) {
#pragma unroll
            for (int j = 0; j < 32; j++)
                if (kb + j > qrow) s[j] = -1e30f;
        }
        float mnew = m;
#pragma unroll
        for (int j = 0; j < 32; j++) mnew = fmaxf(mnew, s[j]);
        float corr = __expf(m - mnew);
        m = mnew;
        l *= corr;
#pragma unroll
        for (int cc = 0; cc < 8; cc++) {
            o[cc].x *= corr; o[cc].y *= corr; o[cc].z *= corr; o[cc].w *= corr;
        }
#pragma unroll
        for (int j = 0; j < 32; j++) {
            float p = __expf(s[j] - mnew);
            l += p;
            s[j] = p;
        }
#pragma unroll
        for (int j = 0; j < 32; j++) {
            float p = s[j];
#pragma unroll
            for (int cc = 0; cc < 8; cc++) {
                float4 vv = Vt[j][cc * 4 + quad];
                o[cc].x = fmaf(p, vv.x, o[cc].x);
                o[cc].y = fmaf(p, vv.y, o[cc].y);
                o[cc].z = fmaf(p, vv.z, o[cc].z);
                o[cc].w = fmaf(p, vv.w, o[cc].w);
            }
        }
    }

    float inv = 1.f / l;
    float* ob = out + (size_t)(b * SS + qrow) * DD + h * DHH;
#pragma unroll
    for (int cc = 0; cc < 8; cc++) {
        float4 v = o[cc];
        v.x *= inv; v.y *= inv; v.z *= inv; v.w *= inv;
        *(float4*)(ob + cc * 16 + quad * 4) = v;
    }
}

// ============================================================================
// Residual-add + LayerNorm, row length 1024, one block/row, 256 threads.
// MODE 0: g_x = LN(aArg + g_tmp)          (aArg = src)
// MODE 1: outArg = LN(g_x + g_tmp)
// Scratch buffers resolved in device code; only harness pointers are args.
// ============================================================================
template<int MODE>
__global__ __launch_bounds__(256) void add_ln_kernel(
    const float* __restrict__ aArg, const float* __restrict__ g,
    const float* __restrict__ beta, float* __restrict__ outArg)
{
    const float* __restrict__ a = (MODE == 0) ? aArg : g_x;
    const float* __restrict__ r = g_tmp;
    float* __restrict__ out = (MODE == 0) ? g_x : outArg;

    __shared__ float red[16];
    const int row = blockIdx.x;
    const int tid = threadIdx.x;

    const float4 va = ((const float4*)(a + (size_t)row * DD))[tid];
    const float4 vr = ((const float4*)(r + (size_t)row * DD))[tid];
    float v0 = va.x + vr.x, v1 = va.y + vr.y, v2 = va.z + vr.z, v3 = va.w + vr.w;

    float s  = v0 + v1 + v2 + v3;
    float sq = v0*v0 + v1*v1 + v2*v2 + v3*v3;
#pragma unroll
    for (int off = 16; off; off >>= 1) {
        s  += __shfl_xor_sync(0xffffffffu, s,  off);
        sq += __shfl_xor_sync(0xffffffffu, sq, off);
    }
    if ((tid & 31) == 0) { red[tid >> 5] = s; red[8 + (tid >> 5)] = sq; }
    __syncthreads();
    s  = red[0] + red[1] + red[2] + red[3] + red[4] + red[5] + red[6] + red[7];
    sq = red[8] + red[9] + red[10] + red[11] + red[12] + red[13] + red[14] + red[15];

    const float mean = s * (1.f / 1024.f);
    const float var  = sq * (1.f / 1024.f) - mean * mean;
    const float inv  = rsqrtf(var + 1e-5f);

    const int col = tid * 4;
    const float4 gg = *(const float4*)(g + col);
    const float4 bb = *(const float4*)(beta + col);
    float4 ov;
    ov.x = (v0 - mean) * inv * gg.x + bb.x;
    ov.y = (v1 - mean) * inv * gg.y + bb.y;
    ov.z = (v2 - mean) * inv * gg.z + bb.z;
    ov.w = (v3 - mean) * inv * gg.w + bb.w;
    ((float4*)(out + (size_t)row * DD))[tid] = ov;
}

// ============================================================================
// launch — kernel launches only; scratch never crosses the host boundary
// ============================================================================
extern "C" void kernel_launch(void* const* d_in, const int* in_sizes, int n_in,
                              void* d_out, int out_size)
{
    const float* src   = (const float*)d_in[0];
    const float* w_qkv = (const float*)d_in[1];
    const float* w_out = (const float*)d_in[2];
    const float* w1    = (const float*)d_in[3];
    const float* b1    = (const float*)d_in[4];
    const float* w2    = (const float*)d_in[5];
    const float* b2    = (const float*)d_in[6];
    const float* g1    = (const float*)d_in[7];
    const float* beta1 = (const float*)d_in[8];
    const float* g2    = (const float*)d_in[9];
    const float* beta2 = (const float*)d_in[10];
    float* out = (float*)d_out;

    // 1) g_qkv = src @ w_qkv                       [8192,3072]
    sgemm_kernel<0,0,0><<<dim3(3*DD/128, ROWS/128), 256>>>(src, w_qkv, nullptr,
                                                           ROWS, 3*DD, DD);
    // 2) g_attn = causal_flash_attention(g_qkv)    [8192,1024]
    attn_kernel<<<dim3(SS/64, HH, BB), 256>>>();
    // 3) g_tmp = g_attn @ w_out
    sgemm_kernel<0,1,1><<<dim3(DD/128, ROWS/128), 256>>>(nullptr, w_out, nullptr,
                                                         ROWS, DD, DD);
    // 4) g_x = LN(src + g_tmp)
    add_ln_kernel<0><<<ROWS, 256>>>(src, g1, beta1, nullptr);
    // 5) g_ff1 = relu(g_x @ w1 + b1)
    sgemm_kernel<2,2,2><<<dim3(DFF/128, ROWS/128), 256>>>(nullptr, w1, b1,
                                                          ROWS, DFF, DD);
    // 6) g_tmp = g_ff1 @ w2 + b2
    sgemm_kernel<1,3,1><<<dim3(DD/128, ROWS/128), 256>>>(nullptr, w2, b2,
                                                         ROWS, DD, DFF);
    // 7) out = LN(g_x + g_tmp)
    add_ln_kernel<1><<<ROWS, 256>>>(nullptr, g2, beta2, out);
}